// round 6
// baseline (speedup 1.0000x reference)
#include <cuda_runtime.h>
#include <cuda_bf16.h>
#include <stdint.h>
#include <string.h>

#define N_NODES 100000
#define N_EDGES 1600000
#define BN_EPS  1e-5f

// ---------------------------------------------------------------------------
// Device scratch
// ---------------------------------------------------------------------------
__device__ __align__(16) float g_aggr[(size_t)N_NODES * 64];
// Weight image: 10 K-chunks of 32 (chunks 0-1 = W1, 2-9 = W2).
// Chunk c @ c*32768: hi plane [256 n][32 k] bf16 swizzled (16384 B), lo @ +16384.
__device__ __align__(16) unsigned char g_Wimg[327680];
// folded BN: y = v*s + o, then ReLU
__device__ float g_s1[256], g_o1[256], g_s2[256], g_o2[256];

// ---------------------------------------------------------------------------
// Swizzle helpers (shared by prep-writer and mma-reader)
// B plane: row n (N dim) = 64 B; 16B-chunk c in [0,4): c' = c ^ ((n>>1)&3)
// A/H plane: row r = 512 B; 16B-chunk cc in [0,32): low 3 bits XOR r
// ---------------------------------------------------------------------------
__device__ __forceinline__ uint32_t bswz(int n, int k) {
    int c = (k >> 3) ^ ((n >> 1) & 3);
    return (uint32_t)(n * 64 + c * 16 + (k & 7) * 2);
}
__device__ __forceinline__ uint32_t aswz(int r, int k) {
    int cc = k >> 3;
    int ccp = (cc & 24) | ((cc ^ r) & 7);
    return (uint32_t)(r * 512 + ccp * 16 + (k & 7) * 2);
}

// ---------------------------------------------------------------------------
// Kernel 1: aggr = x
// ---------------------------------------------------------------------------
__global__ void k_init_aggr(const float* __restrict__ x) {
    int i = blockIdx.x * blockDim.x + threadIdx.x;
    if (i < N_NODES * 16) {
        reinterpret_cast<float4*>(g_aggr)[i] =
            reinterpret_cast<const float4*>(x)[i];
    }
}

// ---------------------------------------------------------------------------
// Kernel 2: scatter-add  aggr[dst] += x[src]  (red.global.add.v4.f32)
// Half-warp per edge; indices loaded once, broadcast via shfl.
// ---------------------------------------------------------------------------
__global__ void k_scatter(const float* __restrict__ x, const int* __restrict__ ei) {
    int gid = blockIdx.x * blockDim.x + threadIdx.x;
    int e = gid >> 4;
    int c = gid & 15;
    int lane = threadIdx.x & 31;
    int src = 0, dst = 0;
    if ((lane & 15) == 0) {
        src = __ldg(ei + e);
        dst = __ldg(ei + N_EDGES + e);
    }
    src = __shfl_sync(0xffffffffu, src, lane & 16);
    dst = __shfl_sync(0xffffffffu, dst, lane & 16);
    float4 v = __ldg(reinterpret_cast<const float4*>(x) + (size_t)src * 16 + c);
    float* p = g_aggr + (size_t)dst * 64 + c * 4;
    asm volatile("red.global.add.v4.f32 [%0], {%1,%2,%3,%4};"
                 :: "l"(p), "f"(v.x), "f"(v.y), "f"(v.z), "f"(v.w)
                 : "memory");
}

// ---------------------------------------------------------------------------
// Prep: weights -> bf16 hi/lo swizzled chunk images; fold BN
// ---------------------------------------------------------------------------
__global__ void k_prep(const float* __restrict__ W1, const float* __restrict__ W2,
    const float* __restrict__ b1, const float* __restrict__ g1, const float* __restrict__ be1,
    const float* __restrict__ rm1, const float* __restrict__ rv1,
    const float* __restrict__ b2, const float* __restrict__ g2, const float* __restrict__ be2,
    const float* __restrict__ rm2, const float* __restrict__ rv2)
{
    int t = blockIdx.x * 256 + threadIdx.x;
    if (t < 81920) {
        int ci = t >> 13;          // chunk 0..9
        int r  = t & 8191;
        int n  = r >> 5;           // 0..255
        int kl = r & 31;           // 0..31
        float v;
        if (ci < 2) v = W1[(size_t)(ci * 32 + kl) * 256 + n];
        else        v = W2[(size_t)((ci - 2) * 32 + kl) * 256 + n];
        __nv_bfloat16 h = __float2bfloat16(v);
        __nv_bfloat16 l = __float2bfloat16(v - __bfloat162float(h));
        unsigned char* base = g_Wimg + (size_t)ci * 32768;
        uint32_t off = bswz(n, kl);
        *(__nv_bfloat16*)(base + off)         = h;
        *(__nv_bfloat16*)(base + 16384 + off) = l;
    } else if (t < 82432) {
        int i = t - 81920;
        int n = i & 255;
        if (i < 256) { float s = g1[n] * rsqrtf(rv1[n] + BN_EPS); g_s1[n] = s; g_o1[n] = (b1[n] - rm1[n]) * s + be1[n]; }
        else         { float s = g2[n] * rsqrtf(rv2[n] + BN_EPS); g_s2[n] = s; g_o2[n] = (b2[n] - rm2[n]) * s + be2[n]; }
    }
}

// ---------------------------------------------------------------------------
// PTX helpers (arch-agnostic sm_80+)
// ---------------------------------------------------------------------------
__device__ __forceinline__ uint32_t s2u(const void* p) {
    uint32_t a;
    asm("{ .reg .u64 t; cvta.to.shared.u64 t, %1; cvt.u32.u64 %0, t; }" : "=r"(a) : "l"(p));
    return a;
}
__device__ __forceinline__ void ldm4(uint32_t* r, uint32_t addr) {
    asm volatile("ldmatrix.sync.aligned.m8n8.x4.shared.b16 {%0,%1,%2,%3}, [%4];"
                 : "=r"(r[0]), "=r"(r[1]), "=r"(r[2]), "=r"(r[3]) : "r"(addr));
}
__device__ __forceinline__ void mma_bf16(float* c, const uint32_t* a, uint32_t b0, uint32_t b1) {
    asm volatile(
        "mma.sync.aligned.m16n8k16.row.col.f32.bf16.bf16.f32 "
        "{%0,%1,%2,%3}, {%4,%5,%6,%7}, {%8,%9}, {%0,%1,%2,%3};"
        : "+f"(c[0]), "+f"(c[1]), "+f"(c[2]), "+f"(c[3])
        : "r"(a[0]), "r"(a[1]), "r"(a[2]), "r"(a[3]), "r"(b0), "r"(b1));
}
__device__ __forceinline__ void cpa16(uint32_t s, const void* g) {
    asm volatile("cp.async.cg.shared.global [%0], [%1], 16;" :: "r"(s), "l"(g));
}
#define CP_COMMIT() asm volatile("cp.async.commit_group;" ::: "memory")

__device__ __forceinline__ void split_pack(float a, float b, uint32_t& hi, uint32_t& lo) {
    __nv_bfloat16 ah = __float2bfloat16(a), bh = __float2bfloat16(b);
    float ar = a - __bfloat162float(ah);
    float br = b - __bfloat162float(bh);
    __nv_bfloat162 hp = __halves2bfloat162(ah, bh);   // low half = a
    __nv_bfloat162 lp = __floats2bfloat162_rn(ar, br);
    memcpy(&hi, &hp, 4);
    memcpy(&lo, &lp, 4);
}

// ---------------------------------------------------------------------------
// Kernel 3: bf16 mma.sync MLP. CTA = 128 nodes x 256 cols, 512 threads.
// SMEM (from 128B-aligned base):
//   [0, 65536)        A/H hi plane: [128 r][256 k] bf16 swizzled
//   [65536, 131072)   A/H lo plane
//   [131072, 229376)  3 B stages x 32768 (hi @+0, lo @+16384 per stage)
// Epilogue-2 staging (fp32, stride 260) reuses the B-stage region.
// ---------------------------------------------------------------------------
#define H_LO     65536
#define OFF_B0   131072
#define STAGE_SZ 32768
#define SMEM_REQ (229376 + 128)

__global__ __launch_bounds__(512, 1) void k_mlp4(float* __restrict__ out) {
    extern __shared__ unsigned char dyn[];
    uint32_t raw = s2u(dyn);
    uint32_t sb  = (raw + 127u) & ~127u;
    unsigned char* sp = dyn + (sb - raw);

    const int tid  = threadIdx.x;
    const int lane = tid & 31;
    const int w    = tid >> 5;
    const int m_w  = (w >> 2) * 32;
    const int n_w  = (w & 3) * 64;
    const int lr   = lane & 7, lsel = lane >> 3;
    const int arow = lr + (lsel & 1) * 8, acol8 = (lsel >> 1) * 8;
    const int brow = lr + (lsel >> 1) * 8, bcol8 = (lsel & 1) * 8;
    const int gid  = lane >> 2, tg2 = (lane & 3) * 2;
    const int row0 = blockIdx.x * 128;

    // ---- prologue: prefetch chunks 0,1 into stages 0,1 (FULL 32KB each) ----
    #pragma unroll
    for (int j = 0; j < 4; j++)
        cpa16(sb + OFF_B0 + (tid + 512 * j) * 16, g_Wimg + (tid + 512 * j) * 16);
    CP_COMMIT();
    #pragma unroll
    for (int j = 0; j < 4; j++)
        cpa16(sb + OFF_B0 + STAGE_SZ + (tid + 512 * j) * 16,
              g_Wimg + STAGE_SZ + (tid + 512 * j) * 16);
    CP_COMMIT();

    // ---- load h tile [128][64] f32 -> bf16 hi/lo into A/H planes (cols 0-63) ----
    {
        int rr = tid >> 2, q = tid & 3;
        float4 f[4];
        #pragma unroll
        for (int i = 0; i < 4; i++) {
            f[i] = make_float4(0.f, 0.f, 0.f, 0.f);
            if (row0 + rr < N_NODES)
                f[i] = ((const float4*)g_aggr)[(size_t)(row0 + rr) * 16 + q * 4 + i];
        }
        uint32_t hi[8], lo[8];
        #pragma unroll
        for (int i = 0; i < 4; i++) {
            split_pack(f[i].x, f[i].y, hi[2 * i],     lo[2 * i]);
            split_pack(f[i].z, f[i].w, hi[2 * i + 1], lo[2 * i + 1]);
        }
        uint32_t o0 = aswz(rr, q * 16);      // chunk 2q
        uint32_t o1 = aswz(rr, q * 16 + 8);  // chunk 2q+1
        *(uint4*)(sp + o0)        = ((uint4*)hi)[0];
        *(uint4*)(sp + o1)        = ((uint4*)hi)[1];
        *(uint4*)(sp + H_LO + o0) = ((uint4*)lo)[0];
        *(uint4*)(sp + H_LO + o1) = ((uint4*)lo)[1];
    }

    float acc[2][8][4];
    #pragma unroll
    for (int a = 0; a < 2; a++)
        #pragma unroll
        for (int b = 0; b < 8; b++)
            #pragma unroll
            for (int cq = 0; cq < 4; cq++) acc[a][b][cq] = 0.f;

    for (int i = 0; i < 10; i++) {
        if (i < 9) asm volatile("cp.async.wait_group 1;" ::: "memory");
        else       asm volatile("cp.async.wait_group 0;" ::: "memory");
        __syncthreads();   // chunk i visible; all warps done with chunk i-1

        // prefetch chunk i+2 into the stage freed at the last sync
        if (i + 2 <= 9) {
            const unsigned char* g = g_Wimg + (size_t)(i + 2) * STAGE_SZ;
            uint32_t s = sb + OFF_B0 + ((i + 2) % 3) * STAGE_SZ;
            #pragma unroll
            for (int j = 0; j < 4; j++)
                cpa16(s + (tid + 512 * j) * 16, g + (tid + 512 * j) * 16);
            CP_COMMIT();
        }

        const int kA0 = (i < 2) ? i * 32 : (i - 2) * 32;
        const uint32_t bbuf = sb + OFF_B0 + (i % 3) * STAGE_SZ;

        #pragma unroll
        for (int step = 0; step < 2; step++) {
            const int kA = kA0 + step * 16;
            const int kB = step * 16;
            uint32_t Ah[2][4], Al[2][4], Bb[4][4];
            #pragma unroll
            for (int mt = 0; mt < 2; mt++)
                ldm4(Ah[mt], sb + aswz(m_w + mt * 16 + arow, kA + acol8));
            #pragma unroll
            for (int np = 0; np < 4; np++)
                ldm4(Bb[np], bbuf + bswz(n_w + np * 16 + brow, kB + bcol8));
            // hi * hi
            #pragma unroll
            for (int mt = 0; mt < 2; mt++)
                #pragma unroll
                for (int np = 0; np < 4; np++) {
                    mma_bf16(acc[mt][np * 2],     Ah[mt], Bb[np][0], Bb[np][1]);
                    mma_bf16(acc[mt][np * 2 + 1], Ah[mt], Bb[np][2], Bb[np][3]);
                }
            // lo * hi
            #pragma unroll
            for (int mt = 0; mt < 2; mt++)
                ldm4(Al[mt], sb + H_LO + aswz(m_w + mt * 16 + arow, kA + acol8));
            #pragma unroll
            for (int mt = 0; mt < 2; mt++)
                #pragma unroll
                for (int np = 0; np < 4; np++) {
                    mma_bf16(acc[mt][np * 2],     Al[mt], Bb[np][0], Bb[np][1]);
                    mma_bf16(acc[mt][np * 2 + 1], Al[mt], Bb[np][2], Bb[np][3]);
                }
            // hi * lo
            #pragma unroll
            for (int np = 0; np < 4; np++)
                ldm4(Bb[np], bbuf + 16384 + bswz(n_w + np * 16 + brow, kB + bcol8));
            #pragma unroll
            for (int mt = 0; mt < 2; mt++)
                #pragma unroll
                for (int np = 0; np < 4; np++) {
                    mma_bf16(acc[mt][np * 2],     Ah[mt], Bb[np][0], Bb[np][1]);
                    mma_bf16(acc[mt][np * 2 + 1], Ah[mt], Bb[np][2], Bb[np][3]);
                }
        }

        if (i == 1) {
            __syncthreads();   // all warps finished layer-1 reads of A1 region
            // ---- epilogue 1: BN1 + ReLU -> H1 hi/lo planes, reset acc ----
            #pragma unroll
            for (int nt = 0; nt < 8; nt++) {
                int col = n_w + nt * 8 + tg2;
                float2 s = *(const float2*)(g_s1 + col);
                float2 o = *(const float2*)(g_o1 + col);
                #pragma unroll
                for (int mt = 0; mt < 2; mt++) {
                    float* c = acc[mt][nt];
                    float v0 = fmaxf(c[0] * s.x + o.x, 0.f);
                    float v1 = fmaxf(c[1] * s.y + o.y, 0.f);
                    float v2 = fmaxf(c[2] * s.x + o.x, 0.f);
                    float v3 = fmaxf(c[3] * s.y + o.y, 0.f);
                    uint32_t h0, l0, h1, l1r;
                    split_pack(v0, v1, h0, l0);
                    split_pack(v2, v3, h1, l1r);
                    int r0 = m_w + mt * 16 + gid;
                    uint32_t o0 = aswz(r0, col), o1 = aswz(r0 + 8, col);
                    *(uint32_t*)(sp + o0)        = h0;
                    *(uint32_t*)(sp + H_LO + o0) = l0;
                    *(uint32_t*)(sp + o1)        = h1;
                    *(uint32_t*)(sp + H_LO + o1) = l1r;
                    c[0] = c[1] = c[2] = c[3] = 0.f;
                }
            }
            // visibility: next iteration's top __syncthreads
        }
    }

    // ---- epilogue 2: BN2 + ReLU, staged through SMEM for coalesced stores ----
    float* stageF = (float*)(sp + OFF_B0);   // [64][260] fp32
    #pragma unroll
    for (int half = 0; half < 2; half++) {
        __syncthreads();   // first: B stages fully consumed; later: copy done
        if ((m_w >> 6) == half) {
            int mloc = m_w & 63;
            #pragma unroll
            for (int nt = 0; nt < 8; nt++) {
                int col = n_w + nt * 8 + tg2;
                float2 s = *(const float2*)(g_s2 + col);
                float2 o = *(const float2*)(g_o2 + col);
                #pragma unroll
                for (int mt = 0; mt < 2; mt++) {
                    float* c = acc[mt][nt];
                    int r = mloc + mt * 16 + gid;
                    *(float2*)(stageF + r * 260 + col) =
                        make_float2(fmaxf(c[0] * s.x + o.x, 0.f),
                                    fmaxf(c[1] * s.y + o.y, 0.f));
                    *(float2*)(stageF + (r + 8) * 260 + col) =
                        make_float2(fmaxf(c[2] * s.x + o.x, 0.f),
                                    fmaxf(c[3] * s.y + o.y, 0.f));
                }
            }
        }
        __syncthreads();
        #pragma unroll
        for (int j = 0; j < 8; j++) {
            int idx = tid + 512 * j;
            int rr = idx >> 6, c4 = idx & 63;
            int grow = row0 + half * 64 + rr;
            if (grow < N_NODES)
                ((float4*)out)[(size_t)grow * 64 + c4] =
                    *(float4*)(stageF + rr * 260 + c4 * 4);
        }
    }
}

// ---------------------------------------------------------------------------
// Launch
// ---------------------------------------------------------------------------
extern "C" void kernel_launch(void* const* d_in, const int* in_sizes, int n_in,
                              void* d_out, int out_size) {
    const float* x   = (const float*)d_in[0];
    const int*   ei  = (const int*)  d_in[2];
    const float* W1  = (const float*)d_in[3];
    const float* b1  = (const float*)d_in[4];
    const float* g1  = (const float*)d_in[5];
    const float* be1 = (const float*)d_in[6];
    const float* rm1 = (const float*)d_in[7];
    const float* rv1 = (const float*)d_in[8];
    const float* W2  = (const float*)d_in[9];
    const float* b2  = (const float*)d_in[10];
    const float* g2  = (const float*)d_in[11];
    const float* be2 = (const float*)d_in[12];
    const float* rm2 = (const float*)d_in[13];
    const float* rv2 = (const float*)d_in[14];
    float* out = (float*)d_out;

    k_init_aggr<<<(N_NODES * 16 + 255) / 256, 256>>>(x);

    {
        long long total = (long long)N_EDGES * 16;
        k_scatter<<<(int)((total + 255) / 256), 256>>>(x, ei);
    }

    k_prep<<<322, 256>>>(W1, W2, b1, g1, be1, rm1, rv1, b2, g2, be2, rm2, rv2);

    {
        cudaFuncSetAttribute(k_mlp4, cudaFuncAttributeMaxDynamicSharedMemorySize,
                             SMEM_REQ);
        int blocks = (N_NODES + 127) / 128;   // 782
        k_mlp4<<<blocks, 512, SMEM_REQ>>>(out);
    }
    (void)in_sizes; (void)n_in; (void)out_size;
}

// round 8
// speedup vs baseline: 1.1702x; 1.1702x over previous
#include <cuda_runtime.h>
#include <cuda_fp16.h>
#include <stdint.h>
#include <string.h>

#define N_NODES 100000
#define N_EDGES 1600000
#define BN_EPS  1e-5f

// ---------------------------------------------------------------------------
// Device scratch
// ---------------------------------------------------------------------------
__device__ __align__(16) float g_aggr[(size_t)N_NODES * 64];
// Weight image: 10 K-chunks of 32 (chunks 0-1 = W1, 2-9 = W2).
// Chunk c @ c*16384: fp16 HI plane only, [256 n][32 k] swizzled (16384 B).
// (2-term split: C = Ah*Bh + Al*Bh -- B lo plane never needed.)
__device__ __align__(16) unsigned char g_Wimg[163840];
// folded BN: y = v*s + o, then ReLU
__device__ float g_s1[256], g_o1[256], g_s2[256], g_o2[256];

// ---------------------------------------------------------------------------
// Swizzle helpers (shared by prep-writer and mma-reader)
// B plane: row n (N dim) = 64 B; 16B-chunk c in [0,4): c' = c ^ ((n>>1)&3)
// A/H plane: row r = 512 B; 16B-chunk cc in [0,32): low 3 bits XOR r
// ---------------------------------------------------------------------------
__device__ __forceinline__ uint32_t bswz(int n, int k) {
    int c = (k >> 3) ^ ((n >> 1) & 3);
    return (uint32_t)(n * 64 + c * 16 + (k & 7) * 2);
}
__device__ __forceinline__ uint32_t aswz(int r, int k) {
    int cc = k >> 3;
    int ccp = (cc & 24) | ((cc ^ r) & 7);
    return (uint32_t)(r * 512 + ccp * 16 + (k & 7) * 2);
}

// ---------------------------------------------------------------------------
// Kernel 1: aggr = x
// ---------------------------------------------------------------------------
__global__ void k_init_aggr(const float* __restrict__ x) {
    int i = blockIdx.x * blockDim.x + threadIdx.x;
    if (i < N_NODES * 16) {
        reinterpret_cast<float4*>(g_aggr)[i] =
            reinterpret_cast<const float4*>(x)[i];
    }
}

// ---------------------------------------------------------------------------
// Kernel 2: scatter-add  aggr[dst] += x[src]  (red.global.add.v4.f32)
// Half-warp per edge; indices loaded once, broadcast via shfl.
// ---------------------------------------------------------------------------
__global__ void k_scatter(const float* __restrict__ x, const int* __restrict__ ei) {
    int gid = blockIdx.x * blockDim.x + threadIdx.x;
    int e = gid >> 4;
    int c = gid & 15;
    int lane = threadIdx.x & 31;
    int src = 0, dst = 0;
    if ((lane & 15) == 0) {
        src = __ldg(ei + e);
        dst = __ldg(ei + N_EDGES + e);
    }
    src = __shfl_sync(0xffffffffu, src, lane & 16);
    dst = __shfl_sync(0xffffffffu, dst, lane & 16);
    float4 v = __ldg(reinterpret_cast<const float4*>(x) + (size_t)src * 16 + c);
    float* p = g_aggr + (size_t)dst * 64 + c * 4;
    asm volatile("red.global.add.v4.f32 [%0], {%1,%2,%3,%4};"
                 :: "l"(p), "f"(v.x), "f"(v.y), "f"(v.z), "f"(v.w)
                 : "memory");
}

// ---------------------------------------------------------------------------
// Prep: weights -> fp16 hi swizzled chunk images; fold BN
// ---------------------------------------------------------------------------
__global__ void k_prep(const float* __restrict__ W1, const float* __restrict__ W2,
    const float* __restrict__ b1, const float* __restrict__ g1, const float* __restrict__ be1,
    const float* __restrict__ rm1, const float* __restrict__ rv1,
    const float* __restrict__ b2, const float* __restrict__ g2, const float* __restrict__ be2,
    const float* __restrict__ rm2, const float* __restrict__ rv2)
{
    int t = blockIdx.x * 256 + threadIdx.x;
    if (t < 81920) {
        int ci = t >> 13;          // chunk 0..9
        int r  = t & 8191;
        int n  = r >> 5;           // 0..255
        int kl = r & 31;           // 0..31
        float v;
        if (ci < 2) v = W1[(size_t)(ci * 32 + kl) * 256 + n];
        else        v = W2[(size_t)((ci - 2) * 32 + kl) * 256 + n];
        unsigned char* base = g_Wimg + (size_t)ci * 16384;
        *(__half*)(base + bswz(n, kl)) = __float2half_rn(v);
    } else if (t < 82432) {
        int i = t - 81920;
        int n = i & 255;
        if (i < 256) { float s = g1[n] * rsqrtf(rv1[n] + BN_EPS); g_s1[n] = s; g_o1[n] = (b1[n] - rm1[n]) * s + be1[n]; }
        else         { float s = g2[n] * rsqrtf(rv2[n] + BN_EPS); g_s2[n] = s; g_o2[n] = (b2[n] - rm2[n]) * s + be2[n]; }
    }
}

// ---------------------------------------------------------------------------
// PTX helpers (arch-agnostic sm_80+)
// ---------------------------------------------------------------------------
__device__ __forceinline__ uint32_t s2u(const void* p) {
    uint32_t a;
    asm("{ .reg .u64 t; cvta.to.shared.u64 t, %1; cvt.u32.u64 %0, t; }" : "=r"(a) : "l"(p));
    return a;
}
__device__ __forceinline__ void ldm4(uint32_t* r, uint32_t addr) {
    asm volatile("ldmatrix.sync.aligned.m8n8.x4.shared.b16 {%0,%1,%2,%3}, [%4];"
                 : "=r"(r[0]), "=r"(r[1]), "=r"(r[2]), "=r"(r[3]) : "r"(addr));
}
__device__ __forceinline__ void mma_f16(float* c, const uint32_t* a, uint32_t b0, uint32_t b1) {
    asm volatile(
        "mma.sync.aligned.m16n8k16.row.col.f32.f16.f16.f32 "
        "{%0,%1,%2,%3}, {%4,%5,%6,%7}, {%8,%9}, {%0,%1,%2,%3};"
        : "+f"(c[0]), "+f"(c[1]), "+f"(c[2]), "+f"(c[3])
        : "r"(a[0]), "r"(a[1]), "r"(a[2]), "r"(a[3]), "r"(b0), "r"(b1));
}
__device__ __forceinline__ void cpa16(uint32_t s, const void* g) {
    asm volatile("cp.async.cg.shared.global [%0], [%1], 16;" :: "r"(s), "l"(g));
}
#define CP_COMMIT() asm volatile("cp.async.commit_group;" ::: "memory")

// fp16 hi/lo split of a pair of floats, packed as half2 words
__device__ __forceinline__ void split_pack(float a, float b, uint32_t& hi, uint32_t& lo) {
    __half ah = __float2half_rn(a), bh = __float2half_rn(b);
    float ar = a - __half2float(ah);
    float br = b - __half2float(bh);
    __half2 hp = __halves2half2(ah, bh);   // low half = a
    __half2 lp = __floats2half2_rn(ar, br);
    memcpy(&hi, &hp, 4);
    memcpy(&lo, &lp, 4);
}

// ---------------------------------------------------------------------------
// Kernel 3: fp16 2-term mma.sync MLP. CTA = 128 nodes x 256 cols, 512 threads.
// SMEM (from 128B-aligned base):
//   [0, 65536)          A/H hi plane: [128 r][256 k] fp16 swizzled
//   [65536, 131072)     A/H lo plane
//   [131072, 180224)    3 B stages x 16384 (hi plane only)
//   [180224, 213504)    epilogue staging [32][260] fp32 (dedicated)
// ---------------------------------------------------------------------------
#define H_LO     65536
#define OFF_B0   131072
#define STAGE_SZ 16384
#define OFF_ST   180224
#define SMEM_REQ (213504 + 128)

__global__ __launch_bounds__(512, 1) void k_mlp5(float* __restrict__ out) {
    extern __shared__ unsigned char dyn[];
    uint32_t raw = s2u(dyn);
    uint32_t sb  = (raw + 127u) & ~127u;
    unsigned char* sp = dyn + (sb - raw);

    const int tid  = threadIdx.x;
    const int lane = tid & 31;
    const int w    = tid >> 5;
    const int m_w  = (w >> 2) * 32;
    const int n_w  = (w & 3) * 64;
    const int lr   = lane & 7, lsel = lane >> 3;
    const int arow = lr + (lsel & 1) * 8, acol8 = (lsel >> 1) * 8;
    const int brow = lr + (lsel >> 1) * 8, bcol8 = (lsel & 1) * 8;
    const int gid  = lane >> 2, tg2 = (lane & 3) * 2;
    const int row0 = blockIdx.x * 128;

    // ---- prologue: prefetch chunks 0,1 into stages 0,1 (16KB each) ----
    #pragma unroll
    for (int j = 0; j < 2; j++)
        cpa16(sb + OFF_B0 + (tid + 512 * j) * 16, g_Wimg + (tid + 512 * j) * 16);
    CP_COMMIT();
    #pragma unroll
    for (int j = 0; j < 2; j++)
        cpa16(sb + OFF_B0 + STAGE_SZ + (tid + 512 * j) * 16,
              g_Wimg + STAGE_SZ + (tid + 512 * j) * 16);
    CP_COMMIT();

    // ---- load h tile [128][64] f32 -> fp16 hi/lo into A/H planes (cols 0-63) ----
    {
        int rr = tid >> 2, q = tid & 3;
        float4 f[4];
        #pragma unroll
        for (int i = 0; i < 4; i++) {
            f[i] = make_float4(0.f, 0.f, 0.f, 0.f);
            if (row0 + rr < N_NODES)
                f[i] = ((const float4*)g_aggr)[(size_t)(row0 + rr) * 16 + q * 4 + i];
        }
        uint32_t hi[8], lo[8];
        #pragma unroll
        for (int i = 0; i < 4; i++) {
            split_pack(f[i].x, f[i].y, hi[2 * i],     lo[2 * i]);
            split_pack(f[i].z, f[i].w, hi[2 * i + 1], lo[2 * i + 1]);
        }
        uint32_t o0 = aswz(rr, q * 16);      // 16B chunk 2q
        uint32_t o1 = aswz(rr, q * 16 + 8);  // 16B chunk 2q+1
        *(uint4*)(sp + o0)        = ((uint4*)hi)[0];
        *(uint4*)(sp + o1)        = ((uint4*)hi)[1];
        *(uint4*)(sp + H_LO + o0) = ((uint4*)lo)[0];
        *(uint4*)(sp + H_LO + o1) = ((uint4*)lo)[1];
    }

    float acc[2][8][4];
    #pragma unroll
    for (int a = 0; a < 2; a++)
        #pragma unroll
        for (int b = 0; b < 8; b++)
            #pragma unroll
            for (int cq = 0; cq < 4; cq++) acc[a][b][cq] = 0.f;

    for (int i = 0; i < 10; i++) {
        if (i < 9) asm volatile("cp.async.wait_group 1;" ::: "memory");
        else       asm volatile("cp.async.wait_group 0;" ::: "memory");
        __syncthreads();   // chunk i visible; all warps done with chunk i-1

        // prefetch chunk i+2 into the stage freed at the last sync
        if (i + 2 <= 9) {
            const unsigned char* g = g_Wimg + (size_t)(i + 2) * STAGE_SZ;
            uint32_t s = sb + OFF_B0 + ((i + 2) % 3) * STAGE_SZ;
            #pragma unroll
            for (int j = 0; j < 2; j++)
                cpa16(s + (tid + 512 * j) * 16, g + (tid + 512 * j) * 16);
            CP_COMMIT();
        }

        const int kA0 = (i < 2) ? i * 32 : (i - 2) * 32;
        const uint32_t bbuf = sb + OFF_B0 + (i % 3) * STAGE_SZ;

        #pragma unroll
        for (int step = 0; step < 2; step++) {
            const int kA = kA0 + step * 16;
            const int kB = step * 16;
            uint32_t Ah[2][4], Al[2][4], Bb[4][4];
            // issue all loads up front so they overlap the MMA stream
            #pragma unroll
            for (int mt = 0; mt < 2; mt++)
                ldm4(Ah[mt], sb + aswz(m_w + mt * 16 + arow, kA + acol8));
            #pragma unroll
            for (int mt = 0; mt < 2; mt++)
                ldm4(Al[mt], sb + H_LO + aswz(m_w + mt * 16 + arow, kA + acol8));
            #pragma unroll
            for (int np = 0; np < 4; np++)
                ldm4(Bb[np], bbuf + bswz(n_w + np * 16 + brow, kB + bcol8));
            // hi * hi
            #pragma unroll
            for (int mt = 0; mt < 2; mt++)
                #pragma unroll
                for (int np = 0; np < 4; np++) {
                    mma_f16(acc[mt][np * 2],     Ah[mt], Bb[np][0], Bb[np][1]);
                    mma_f16(acc[mt][np * 2 + 1], Ah[mt], Bb[np][2], Bb[np][3]);
                }
            // lo * hi
            #pragma unroll
            for (int mt = 0; mt < 2; mt++)
                #pragma unroll
                for (int np = 0; np < 4; np++) {
                    mma_f16(acc[mt][np * 2],     Al[mt], Bb[np][0], Bb[np][1]);
                    mma_f16(acc[mt][np * 2 + 1], Al[mt], Bb[np][2], Bb[np][3]);
                }
        }

        if (i == 1) {
            __syncthreads();   // all warps finished layer-1 reads of A1 region
            // ---- epilogue 1: BN1 + ReLU -> H1 hi/lo planes, reset acc ----
            #pragma unroll
            for (int nt = 0; nt < 8; nt++) {
                int col = n_w + nt * 8 + tg2;
                float2 s = *(const float2*)(g_s1 + col);
                float2 o = *(const float2*)(g_o1 + col);
                #pragma unroll
                for (int mt = 0; mt < 2; mt++) {
                    float* c = acc[mt][nt];
                    float v0 = fmaxf(c[0] * s.x + o.x, 0.f);
                    float v1 = fmaxf(c[1] * s.y + o.y, 0.f);
                    float v2 = fmaxf(c[2] * s.x + o.x, 0.f);
                    float v3 = fmaxf(c[3] * s.y + o.y, 0.f);
                    uint32_t h0, l0, h1, l1r;
                    split_pack(v0, v1, h0, l0);
                    split_pack(v2, v3, h1, l1r);
                    int r0 = m_w + mt * 16 + gid;
                    uint32_t o0 = aswz(r0, col), o1 = aswz(r0 + 8, col);
                    *(uint32_t*)(sp + o0)        = h0;
                    *(uint32_t*)(sp + H_LO + o0) = l0;
                    *(uint32_t*)(sp + o1)        = h1;
                    *(uint32_t*)(sp + H_LO + o1) = l1r;
                    c[0] = c[1] = c[2] = c[3] = 0.f;
                }
            }
            // visibility: next iteration's top __syncthreads
        }
    }

    // ---- epilogue 2: BN2 + ReLU, 4 quarter-tiles of 32 rows, staged in SMEM ----
    float* stageF = (float*)(sp + OFF_ST);   // [32][260] fp32
    for (int q = 0; q < 4; q++) {
        if ((w >> 2) == q) {   // the 4 warps owning rows [q*32, q*32+32)
            #pragma unroll
            for (int nt = 0; nt < 8; nt++) {
                int col = n_w + nt * 8 + tg2;
                float2 s = *(const float2*)(g_s2 + col);
                float2 o = *(const float2*)(g_o2 + col);
                #pragma unroll
                for (int mt = 0; mt < 2; mt++) {
                    float* c = acc[mt][nt];
                    int r = mt * 16 + gid;
                    *(float2*)(stageF + r * 260 + col) =
                        make_float2(fmaxf(c[0] * s.x + o.x, 0.f),
                                    fmaxf(c[1] * s.y + o.y, 0.f));
                    *(float2*)(stageF + (r + 8) * 260 + col) =
                        make_float2(fmaxf(c[2] * s.x + o.x, 0.f),
                                    fmaxf(c[3] * s.y + o.y, 0.f));
                }
            }
        }
        __syncthreads();
        #pragma unroll
        for (int j = 0; j < 4; j++) {
            int idx = tid + 512 * j;          // 0..2047
            int rr = idx >> 6, c4 = idx & 63;
            int grow = row0 + q * 32 + rr;
            if (grow < N_NODES)
                ((float4*)out)[(size_t)grow * 64 + c4] =
                    *(float4*)(stageF + rr * 260 + c4 * 4);
        }
        __syncthreads();   // staging free for next quarter
    }
}

// ---------------------------------------------------------------------------
// Launch
// ---------------------------------------------------------------------------
extern "C" void kernel_launch(void* const* d_in, const int* in_sizes, int n_in,
                              void* d_out, int out_size) {
    const float* x   = (const float*)d_in[0];
    const int*   ei  = (const int*)  d_in[2];
    const float* W1  = (const float*)d_in[3];
    const float* b1  = (const float*)d_in[4];
    const float* g1  = (const float*)d_in[5];
    const float* be1 = (const float*)d_in[6];
    const float* rm1 = (const float*)d_in[7];
    const float* rv1 = (const float*)d_in[8];
    const float* W2  = (const float*)d_in[9];
    const float* b2  = (const float*)d_in[10];
    const float* g2  = (const float*)d_in[11];
    const float* be2 = (const float*)d_in[12];
    const float* rm2 = (const float*)d_in[13];
    const float* rv2 = (const float*)d_in[14];
    float* out = (float*)d_out;

    k_init_aggr<<<(N_NODES * 16 + 255) / 256, 256>>>(x);

    {
        long long total = (long long)N_EDGES * 16;
        k_scatter<<<(int)((total + 255) / 256), 256>>>(x, ei);
    }

    k_prep<<<322, 256>>>(W1, W2, b1, g1, be1, rm1, rv1, b2, g2, be2, rm2, rv2);

    {
        cudaFuncSetAttribute(k_mlp5, cudaFuncAttributeMaxDynamicSharedMemorySize,
                             SMEM_REQ);
        int blocks = (N_NODES + 127) / 128;   // 782
        k_mlp5<<<blocks, 512, SMEM_REQ>>>(out);
    }
    (void)in_sizes; (void)n_in; (void)out_size;
}

// round 9
// speedup vs baseline: 1.3404x; 1.1455x over previous
#include <cuda_runtime.h>
#include <cuda_fp16.h>
#include <stdint.h>
#include <string.h>

#define N_NODES 100000
#define N_EDGES 1600000
#define BN_EPS  1e-5f

// ---------------------------------------------------------------------------
// Device scratch
// ---------------------------------------------------------------------------
__device__ __align__(16) float g_aggr[(size_t)N_NODES * 64];
// Weight image: 10 K-chunks of 32 (chunks 0-1 = W1, 2-9 = W2).
// Chunk c @ c*16384: fp16 HI plane only, [256 n][32 k] swizzled (16384 B).
__device__ __align__(16) unsigned char g_Wimg[163840];
// folded BN: y = v*s + o, then ReLU
__device__ float g_s1[256], g_o1[256], g_s2[256], g_o2[256];

// ---------------------------------------------------------------------------
// Swizzle helpers
// B plane: row n (N dim) = 64 B; 16B-chunk c in [0,4): c' = c ^ ((n>>1)&3)
// A/H plane: row r = 512 B; 16B-chunk cc in [0,32): low 3 bits XOR r
// ---------------------------------------------------------------------------
__device__ __forceinline__ uint32_t bswz(int n, int k) {
    int c = (k >> 3) ^ ((n >> 1) & 3);
    return (uint32_t)(n * 64 + c * 16 + (k & 7) * 2);
}
__device__ __forceinline__ uint32_t aswz(int r, int k) {
    int cc = k >> 3;
    int ccp = (cc & 24) | ((cc ^ r) & 7);
    return (uint32_t)(r * 512 + ccp * 16 + (k & 7) * 2);
}

// ---------------------------------------------------------------------------
// Kernel 1: aggr = x
// ---------------------------------------------------------------------------
__global__ void k_init_aggr(const float* __restrict__ x) {
    int i = blockIdx.x * blockDim.x + threadIdx.x;
    if (i < N_NODES * 16) {
        reinterpret_cast<float4*>(g_aggr)[i] =
            reinterpret_cast<const float4*>(x)[i];
    }
}

// ---------------------------------------------------------------------------
// Kernel 2: scatter-add  aggr[dst] += x[src]  (red.global.add.v4.f32)
// ---------------------------------------------------------------------------
__global__ void k_scatter(const float* __restrict__ x, const int* __restrict__ ei) {
    int gid = blockIdx.x * blockDim.x + threadIdx.x;
    int e = gid >> 4;
    int c = gid & 15;
    int lane = threadIdx.x & 31;
    int src = 0, dst = 0;
    if ((lane & 15) == 0) {
        src = __ldg(ei + e);
        dst = __ldg(ei + N_EDGES + e);
    }
    src = __shfl_sync(0xffffffffu, src, lane & 16);
    dst = __shfl_sync(0xffffffffu, dst, lane & 16);
    float4 v = __ldg(reinterpret_cast<const float4*>(x) + (size_t)src * 16 + c);
    float* p = g_aggr + (size_t)dst * 64 + c * 4;
    asm volatile("red.global.add.v4.f32 [%0], {%1,%2,%3,%4};"
                 :: "l"(p), "f"(v.x), "f"(v.y), "f"(v.z), "f"(v.w)
                 : "memory");
}

// ---------------------------------------------------------------------------
// Prep: weights -> fp16 hi swizzled chunk images; fold BN
// ---------------------------------------------------------------------------
__global__ void k_prep(const float* __restrict__ W1, const float* __restrict__ W2,
    const float* __restrict__ b1, const float* __restrict__ g1, const float* __restrict__ be1,
    const float* __restrict__ rm1, const float* __restrict__ rv1,
    const float* __restrict__ b2, const float* __restrict__ g2, const float* __restrict__ be2,
    const float* __restrict__ rm2, const float* __restrict__ rv2)
{
    int t = blockIdx.x * 256 + threadIdx.x;
    if (t < 81920) {
        int ci = t >> 13;          // chunk 0..9
        int r  = t & 8191;
        int n  = r >> 5;           // 0..255
        int kl = r & 31;           // 0..31
        float v;
        if (ci < 2) v = W1[(size_t)(ci * 32 + kl) * 256 + n];
        else        v = W2[(size_t)((ci - 2) * 32 + kl) * 256 + n];
        unsigned char* base = g_Wimg + (size_t)ci * 16384;
        *(__half*)(base + bswz(n, kl)) = __float2half_rn(v);
    } else if (t < 82432) {
        int i = t - 81920;
        int n = i & 255;
        if (i < 256) { float s = g1[n] * rsqrtf(rv1[n] + BN_EPS); g_s1[n] = s; g_o1[n] = (b1[n] - rm1[n]) * s + be1[n]; }
        else         { float s = g2[n] * rsqrtf(rv2[n] + BN_EPS); g_s2[n] = s; g_o2[n] = (b2[n] - rm2[n]) * s + be2[n]; }
    }
}

// ---------------------------------------------------------------------------
// PTX helpers (arch-agnostic sm_80+)
// ---------------------------------------------------------------------------
__device__ __forceinline__ uint32_t s2u(const void* p) {
    uint32_t a;
    asm("{ .reg .u64 t; cvta.to.shared.u64 t, %1; cvt.u32.u64 %0, t; }" : "=r"(a) : "l"(p));
    return a;
}
__device__ __forceinline__ void ldm4(uint32_t* r, uint32_t addr) {
    asm volatile("ldmatrix.sync.aligned.m8n8.x4.shared.b16 {%0,%1,%2,%3}, [%4];"
                 : "=r"(r[0]), "=r"(r[1]), "=r"(r[2]), "=r"(r[3]) : "r"(addr));
}
__device__ __forceinline__ void mma_f16(float* c, const uint32_t* a, uint32_t b0, uint32_t b1) {
    asm volatile(
        "mma.sync.aligned.m16n8k16.row.col.f32.f16.f16.f32 "
        "{%0,%1,%2,%3}, {%4,%5,%6,%7}, {%8,%9}, {%0,%1,%2,%3};"
        : "+f"(c[0]), "+f"(c[1]), "+f"(c[2]), "+f"(c[3])
        : "r"(a[0]), "r"(a[1]), "r"(a[2]), "r"(a[3]), "r"(b0), "r"(b1));
}
__device__ __forceinline__ void cpa16(uint32_t s, const void* g) {
    asm volatile("cp.async.cg.shared.global [%0], [%1], 16;" :: "r"(s), "l"(g));
}
#define CP_COMMIT() asm volatile("cp.async.commit_group;" ::: "memory")

// fp16 hi/lo split of a pair of floats, packed as half2 words
__device__ __forceinline__ void split_pack(float a, float b, uint32_t& hi, uint32_t& lo) {
    __half ah = __float2half_rn(a), bh = __float2half_rn(b);
    float ar = a - __half2float(ah);
    float br = b - __half2float(bh);
    __half2 hp = __halves2half2(ah, bh);   // low half = a
    __half2 lp = __floats2half2_rn(ar, br);
    memcpy(&hi, &hp, 4);
    memcpy(&lo, &lp, 4);
}

// ---------------------------------------------------------------------------
// Kernel 3: fp16 2-term mma.sync MLP.
// CTA = 64 nodes x 256 cols, 256 threads (8 warps: 2 m-groups x 4 n-groups),
// sized for 2 CTAs/SM so barrier/pipeline stalls of one CTA hide under the
// other CTA's MMA stream.
// SMEM per CTA (from 128B-aligned base):
//   [0, 32768)         A/H hi plane: [64 r][256 k] fp16 swizzled
//   [32768, 65536)     A/H lo plane
//   [65536, 114688)    3 B stages x 16384 (hi plane only)
// Epilogue staging [32][260] fp32 reuses the B-stage region.
// ---------------------------------------------------------------------------
#define H_LO     32768
#define OFF_B0   65536
#define STAGE_SZ 16384
#define SMEM_REQ (114688 + 128)

__global__ __launch_bounds__(256, 2) void k_mlp6(float* __restrict__ out) {
    extern __shared__ unsigned char dyn[];
    uint32_t raw = s2u(dyn);
    uint32_t sb  = (raw + 127u) & ~127u;
    unsigned char* sp = dyn + (sb - raw);

    const int tid  = threadIdx.x;
    const int lane = tid & 31;
    const int w    = tid >> 5;            // 0..7
    const int m_w  = (w >> 2) * 32;       // 0 or 32
    const int n_w  = (w & 3) * 64;        // 0,64,128,192
    const int lr   = lane & 7, lsel = lane >> 3;
    const int arow = lr + (lsel & 1) * 8, acol8 = (lsel >> 1) * 8;
    const int brow = lr + (lsel >> 1) * 8, bcol8 = (lsel & 1) * 8;
    const int gid  = lane >> 2, tg2 = (lane & 3) * 2;
    const int row0 = blockIdx.x * 64;

    // ---- prologue: prefetch chunks 0,1 into stages 0,1 (16KB each) ----
    #pragma unroll
    for (int j = 0; j < 4; j++)
        cpa16(sb + OFF_B0 + (tid + 256 * j) * 16, g_Wimg + (tid + 256 * j) * 16);
    CP_COMMIT();
    #pragma unroll
    for (int j = 0; j < 4; j++)
        cpa16(sb + OFF_B0 + STAGE_SZ + (tid + 256 * j) * 16,
              g_Wimg + STAGE_SZ + (tid + 256 * j) * 16);
    CP_COMMIT();

    // ---- load h tile [64][64] f32 -> fp16 hi/lo into A/H planes (cols 0-63) ----
    {
        int rr = tid >> 2, q = tid & 3;   // rr 0..63
        float4 f[4];
        #pragma unroll
        for (int i = 0; i < 4; i++) {
            f[i] = make_float4(0.f, 0.f, 0.f, 0.f);
            if (row0 + rr < N_NODES)
                f[i] = ((const float4*)g_aggr)[(size_t)(row0 + rr) * 16 + q * 4 + i];
        }
        uint32_t hi[8], lo[8];
        #pragma unroll
        for (int i = 0; i < 4; i++) {
            split_pack(f[i].x, f[i].y, hi[2 * i],     lo[2 * i]);
            split_pack(f[i].z, f[i].w, hi[2 * i + 1], lo[2 * i + 1]);
        }
        uint32_t o0 = aswz(rr, q * 16);
        uint32_t o1 = aswz(rr, q * 16 + 8);
        *(uint4*)(sp + o0)        = ((uint4*)hi)[0];
        *(uint4*)(sp + o1)        = ((uint4*)hi)[1];
        *(uint4*)(sp + H_LO + o0) = ((uint4*)lo)[0];
        *(uint4*)(sp + H_LO + o1) = ((uint4*)lo)[1];
    }

    float acc[2][8][4];
    #pragma unroll
    for (int a = 0; a < 2; a++)
        #pragma unroll
        for (int b = 0; b < 8; b++)
            #pragma unroll
            for (int cq = 0; cq < 4; cq++) acc[a][b][cq] = 0.f;

    for (int i = 0; i < 10; i++) {
        if (i < 9) asm volatile("cp.async.wait_group 1;" ::: "memory");
        else       asm volatile("cp.async.wait_group 0;" ::: "memory");
        __syncthreads();   // chunk i visible; all warps done with chunk i-1

        // prefetch chunk i+2 into the stage freed at the last sync
        if (i + 2 <= 9) {
            const unsigned char* g = g_Wimg + (size_t)(i + 2) * STAGE_SZ;
            uint32_t s = sb + OFF_B0 + ((i + 2) % 3) * STAGE_SZ;
            #pragma unroll
            for (int j = 0; j < 4; j++)
                cpa16(s + (tid + 256 * j) * 16, g + (tid + 256 * j) * 16);
            CP_COMMIT();
        }

        const int kA0 = (i < 2) ? i * 32 : (i - 2) * 32;
        const uint32_t bbuf = sb + OFF_B0 + (i % 3) * STAGE_SZ;

        #pragma unroll
        for (int step = 0; step < 2; step++) {
            const int kA = kA0 + step * 16;
            const int kB = step * 16;
            uint32_t Ah[2][4], Al[2][4], Bb[4][4];
            #pragma unroll
            for (int mt = 0; mt < 2; mt++)
                ldm4(Ah[mt], sb + aswz(m_w + mt * 16 + arow, kA + acol8));
            #pragma unroll
            for (int mt = 0; mt < 2; mt++)
                ldm4(Al[mt], sb + H_LO + aswz(m_w + mt * 16 + arow, kA + acol8));
            #pragma unroll
            for (int np = 0; np < 4; np++)
                ldm4(Bb[np], bbuf + bswz(n_w + np * 16 + brow, kB + bcol8));
            // hi * hi
            #pragma unroll
            for (int mt = 0; mt < 2; mt++)
                #pragma unroll
                for (int np = 0; np < 4; np++) {
                    mma_f16(acc[mt][np * 2],     Ah[mt], Bb[np][0], Bb[np][1]);
                    mma_f16(acc[mt][np * 2 + 1], Ah[mt], Bb[np][2], Bb[np][3]);
                }
            // lo * hi
            #pragma unroll
            for (int mt = 0; mt < 2; mt++)
                #pragma unroll
                for (int np = 0; np < 4; np++) {
                    mma_f16(acc[mt][np * 2],     Al[mt], Bb[np][0], Bb[np][1]);
                    mma_f16(acc[mt][np * 2 + 1], Al[mt], Bb[np][2], Bb[np][3]);
                }
        }

        if (i == 1) {
            __syncthreads();   // all warps finished layer-1 reads of A1 region
            // ---- epilogue 1: BN1 + ReLU -> H1 hi/lo planes, reset acc ----
            #pragma unroll
            for (int nt = 0; nt < 8; nt++) {
                int col = n_w + nt * 8 + tg2;
                float2 s = *(const float2*)(g_s1 + col);
                float2 o = *(const float2*)(g_o1 + col);
                #pragma unroll
                for (int mt = 0; mt < 2; mt++) {
                    float* c = acc[mt][nt];
                    float v0 = fmaxf(c[0] * s.x + o.x, 0.f);
                    float v1 = fmaxf(c[1] * s.y + o.y, 0.f);
                    float v2 = fmaxf(c[2] * s.x + o.x, 0.f);
                    float v3 = fmaxf(c[3] * s.y + o.y, 0.f);
                    uint32_t h0, l0, h1, l1r;
                    split_pack(v0, v1, h0, l0);
                    split_pack(v2, v3, h1, l1r);
                    int r0 = m_w + mt * 16 + gid;
                    uint32_t o0 = aswz(r0, col), o1 = aswz(r0 + 8, col);
                    *(uint32_t*)(sp + o0)        = h0;
                    *(uint32_t*)(sp + H_LO + o0) = l0;
                    *(uint32_t*)(sp + o1)        = h1;
                    *(uint32_t*)(sp + H_LO + o1) = l1r;
                    c[0] = c[1] = c[2] = c[3] = 0.f;
                }
            }
            // visibility: next iteration's top __syncthreads
        }
    }

    // ---- epilogue 2: BN2 + ReLU, 2 half-tiles of 32 rows, staged in SMEM ----
    float* stageF = (float*)(sp + OFF_B0);   // [32][260] fp32 (B stages done)
    for (int q = 0; q < 2; q++) {
        __syncthreads();   // first: B stages consumed; later: copy done
        if ((w >> 2) == q) {   // the 4 warps owning rows [q*32, q*32+32)
            #pragma unroll
            for (int nt = 0; nt < 8; nt++) {
                int col = n_w + nt * 8 + tg2;
                float2 s = *(const float2*)(g_s2 + col);
                float2 o = *(const float2*)(g_o2 + col);
                #pragma unroll
                for (int mt = 0; mt < 2; mt++) {
                    float* c = acc[mt][nt];
                    int r = mt * 16 + gid;
                    *(float2*)(stageF + r * 260 + col) =
                        make_float2(fmaxf(c[0] * s.x + o.x, 0.f),
                                    fmaxf(c[1] * s.y + o.y, 0.f));
                    *(float2*)(stageF + (r + 8) * 260 + col) =
                        make_float2(fmaxf(c[2] * s.x + o.x, 0.f),
                                    fmaxf(c[3] * s.y + o.y, 0.f));
                }
            }
        }
        __syncthreads();
        #pragma unroll
        for (int j = 0; j < 8; j++) {
            int idx = tid + 256 * j;          // 0..2047
            int rr = idx >> 6, c4 = idx & 63;
            int grow = row0 + q * 32 + rr;
            if (grow < N_NODES)
                ((float4*)out)[(size_t)grow * 64 + c4] =
                    *(float4*)(stageF + rr * 260 + c4 * 4);
        }
    }
}

// ---------------------------------------------------------------------------
// Launch
// ---------------------------------------------------------------------------
extern "C" void kernel_launch(void* const* d_in, const int* in_sizes, int n_in,
                              void* d_out, int out_size) {
    const float* x   = (const float*)d_in[0];
    const int*   ei  = (const int*)  d_in[2];
    const float* W1  = (const float*)d_in[3];
    const float* b1  = (const float*)d_in[4];
    const float* g1  = (const float*)d_in[5];
    const float* be1 = (const float*)d_in[6];
    const float* rm1 = (const float*)d_in[7];
    const float* rv1 = (const float*)d_in[8];
    const float* W2  = (const float*)d_in[9];
    const float* b2  = (const float*)d_in[10];
    const float* g2  = (const float*)d_in[11];
    const float* be2 = (const float*)d_in[12];
    const float* rm2 = (const float*)d_in[13];
    const float* rv2 = (const float*)d_in[14];
    float* out = (float*)d_out;

    k_init_aggr<<<(N_NODES * 16 + 255) / 256, 256>>>(x);

    {
        long long total = (long long)N_EDGES * 16;
        k_scatter<<<(int)((total + 255) / 256), 256>>>(x, ei);
    }

    k_prep<<<322, 256>>>(W1, W2, b1, g1, be1, rm1, rv1, b2, g2, be2, rm2, rv2);

    {
        cudaFuncSetAttribute(k_mlp6, cudaFuncAttributeMaxDynamicSharedMemorySize,
                             SMEM_REQ);
        int blocks = (N_NODES + 63) / 64;   // 1563
        k_mlp6<<<blocks, 256, SMEM_REQ>>>(out);
    }
    (void)in_sizes; (void)n_in; (void)out_size;
}